// round 12
// baseline (speedup 1.0000x reference)
#include <cuda_runtime.h>
#include <cstdint>

#define BATCH 8
#define NPTS  4096
#define MPTS  2048
#define FDIM  64
#define KNBR  64
#define NG    (BATCH*MPTS)
#define CAP   256

// output segments (float32): x_out [NG,128] | pos_out [NG,3] | batch_out [NG]
#define XSEG   (NG*128)
#define PBASE  XSEG
#define BBASE  (XSEG + NG*3)
#define TOTSEG (BBASE + NG)

__device__ float  g_q[NG*3];
__device__ float4 g_pos4[BATCH*NPTS];
__device__ volatile int g_prog[BATCH];
__device__ int    g_ctr;

typedef unsigned long long u64;

__device__ __forceinline__ unsigned rmax32(unsigned v) {
    unsigned r;
    asm("redux.sync.max.u32 %0, %1, 0xffffffff;" : "=r"(r) : "r"(v));
    return r;
}
__device__ __forceinline__ float ldcv(const float* p) {
    float v; asm volatile("ld.global.cv.f32 %0, [%1];" : "=f"(v) : "l"(p)); return v;
}
__device__ __forceinline__ float tf32r(float v) {
    unsigned u; asm("cvt.rna.tf32.f32 %0, %1;" : "=r"(u) : "f"(v));
    return __uint_as_float(u);
}
__device__ __forceinline__ void mma8(float* c, const unsigned* a, const unsigned* b) {
    asm("mma.sync.aligned.m16n8k8.row.col.f32.tf32.tf32.f32 "
        "{%0,%1,%2,%3},{%4,%5,%6,%7},{%8,%9},{%0,%1,%2,%3};"
        : "+f"(c[0]), "+f"(c[1]), "+f"(c[2]), "+f"(c[3])
        : "r"(a[0]), "r"(a[1]), "r"(a[2]), "r"(a[3]), "r"(b[0]), "r"(b[1]));
}
__device__ __forceinline__ void mma4(float* c, const unsigned* a, unsigned b0) {
    asm("mma.sync.aligned.m16n8k4.row.col.f32.tf32.tf32.f32 "
        "{%0,%1,%2,%3},{%4,%5},{%6},{%0,%1,%2,%3};"
        : "+f"(c[0]), "+f"(c[1]), "+f"(c[2]), "+f"(c[3])
        : "r"(a[0]), "r"(a[1]), "r"(b0));
}
__device__ __forceinline__ void cbar() {
    asm volatile("bar.sync 1, 256;" ::: "memory");
}

// ---------------- smem layout (floats); all matrices stride 68 -------------
#define W1H 0          // 64x68  (k=67 zeroed)
#define W1L 4352
#define W2H 8704
#define W2L 13056
#define W3H 17408      // 128x68
#define W3L 26112
#define B1O 34816
#define B2O 34880
#define B3O 34944
#define FH  35072      // feat hi 64x68  (H2 hi reuses)
#define FL  39424      // feat lo        (H2 lo reuses)
#define H1H 43776
#define H1L 48128
#define ROO 52480      // 4 mtiles x 128
#define CDO 52992      // 256
#define CIO 53248      // 256 (int)
#define NLO 53504      // 64 (int)
#define MSO 53568
#define SM_TOT 53600   // 214,400 bytes
#define FPSO FH        // producer scratch (12288 floats, consumer-phase free)

// ============================================================================
__global__ void __launch_bounds__(256)
init_kernel(const float* __restrict__ pos)
{
    int i = blockIdx.x * 256 + threadIdx.x;
    if (i == 0) g_ctr = 0;
    if (i < BATCH) g_prog[i] = 0;
    if (i < BATCH * NPTS) {
        const float* p = pos + (size_t)i * 3;
        g_pos4[i] = make_float4(p[0], p[1], p[2], 0.0f);
    }
}

// ============================================================================
__global__ void __launch_bounds__(512)
fused_kernel(const float* __restrict__ x, const float* __restrict__ pos,
             const float* __restrict__ W1, const float* __restrict__ b1,
             const float* __restrict__ W2, const float* __restrict__ b2,
             const float* __restrict__ W3, const float* __restrict__ b3,
             float* __restrict__ dout, int out_size)
{
    extern __shared__ float sm[];
    const int tid = threadIdx.x;

    // ---- stage weights transposed [c][k], 3xTF32 hi/lo split ----
    for (int idx = tid; idx < 67 * 64; idx += 512) {
        int k = idx >> 6, c = idx & 63;
        float v = W1[idx], hi = tf32r(v);
        sm[W1H + c*68 + k] = hi;
        sm[W1L + c*68 + k] = tf32r(v - hi);
    }
    for (int idx = tid; idx < 64 * 64; idx += 512) {
        int k = idx >> 6, c = idx & 63;
        float v = W2[idx], hi = tf32r(v);
        sm[W2H + c*68 + k] = hi;
        sm[W2L + c*68 + k] = tf32r(v - hi);
    }
    for (int idx = tid; idx < 64 * 128; idx += 512) {
        int k = idx >> 7, c = idx & 127;
        float v = W3[idx], hi = tf32r(v);
        sm[W3H + c*68 + k] = hi;
        sm[W3L + c*68 + k] = tf32r(v - hi);
    }
    if (tid < 64) {
        sm[W1H + tid*68 + 67] = 0.0f;
        sm[W1L + tid*68 + 67] = 0.0f;
        sm[B1O + tid] = b1[tid]; sm[B2O + tid] = b2[tid];
    }
    if (tid < 128) sm[B3O + tid] = b3[tid];
    __syncthreads();

    // ======================= producer: FPS (blocks 0..7, 512 thr) ==========
    if (blockIdx.x < BATCH) {
        __shared__ u64 rd2[32];
        float* sp = sm + FPSO;                  // compact stride-3 pos cache
        const int b = blockIdx.x;
        const int lane = tid & 31, w = tid >> 5;
        const float* pb = pos + (size_t)b * NPTS * 3;

        for (int i = tid; i < NPTS * 3; i += 512) sp[i] = pb[i];
        __syncthreads();

        float px[8], py[8], pz[8], md[8];
#pragma unroll
        for (int j = 0; j < 8; j++) {
            int idx = j * 512 + tid;
            px[j] = sp[3*idx]; py[j] = sp[3*idx+1]; pz[j] = sp[3*idx+2];
            md[j] = __int_as_float(0x7f800000);
        }

        if (tid == 0) {
            int g = b * MPTS;
            g_q[3*g] = sp[0]; g_q[3*g+1] = sp[1]; g_q[3*g+2] = sp[2];
            if (out_size >= BBASE) {
                dout[PBASE+3*g] = sp[0]; dout[PBASE+3*g+1] = sp[1]; dout[PBASE+3*g+2] = sp[2];
            }
            if (out_size >= TOTSEG) dout[BBASE+g] = (float)b;
            __threadfence();
            g_prog[b] = 1;
        }
        __syncthreads();

        int cur = 0;
        for (int step = 1; step < MPTS; step++) {
            float lx = sp[3*cur], ly = sp[3*cur+1], lz = sp[3*cur+2];
            float bd = -1.0f; int bi = 0;
#pragma unroll
            for (int j = 0; j < 8; j++) {
                float dx = __fadd_rn(px[j], -lx);
                float dy = __fadd_rn(py[j], -ly);
                float dz = __fadd_rn(pz[j], -lz);
                float d  = __fadd_rn(__fadd_rn(__fmul_rn(dx,dx), __fmul_rn(dy,dy)),
                                     __fmul_rn(dz,dz));
                float m = fminf(md[j], d);
                md[j] = m;
                if (m > bd) { bd = m; bi = j * 512 + tid; }
            }
            unsigned dbits = __float_as_uint(bd);
            unsigned mx   = rmax32(dbits);
            unsigned cand = (dbits == mx) ? (0xFFFFFFFFu - (unsigned)bi) : 0u;
            unsigned cmx  = rmax32(cand);
            if (lane == 0) rd2[(step & 1) * 16 + w] = ((u64)mx << 32) | (u64)cmx;
            __syncthreads();
            const u64* rr = &rd2[(step & 1) * 16];
            u64 best = rr[0];
#pragma unroll
            for (int i = 1; i < 16; i++) { u64 v = rr[i]; if (v > best) best = v; }
            cur = (int)(0xFFFFFFFFu - (unsigned)best);
            if (tid == 0) {
                int g = b * MPTS + step;
                float qx = sp[3*cur], qy = sp[3*cur+1], qz = sp[3*cur+2];
                g_q[3*g] = qx; g_q[3*g+1] = qy; g_q[3*g+2] = qz;
                if (out_size >= BBASE) {
                    dout[PBASE+3*g] = qx; dout[PBASE+3*g+1] = qy; dout[PBASE+3*g+2] = qz;
                }
                if (out_size >= TOTSEG) dout[BBASE+g] = (float)b;
                __threadfence();
                g_prog[b] = step + 1;
            }
        }
        __syncthreads();
    }

    // ======================= consumer: warps 0..7 only ======================
    if (tid >= 256) return;

    int*   msi = (int*)(sm + MSO);
    float* msf = sm + MSO + 4;
    int*   nl  = (int*)(sm + NLO);
    int*   ci  = (int*)(sm + CIO);

    const int lane = tid & 31, w = tid >> 5;
    const int mtile = w >> 1, half = w & 1;
    const int mr = mtile * 16;
    const int lr = lane >> 2, lc = lane & 3;   // frag row/col decomp
    const int e = tid >> 2, sub = tid & 3;
    const float R2 = (float)(0.15 * 0.15);

    for (;;) {
        if (tid == 0) msi[0] = atomicAdd(&g_ctr, 1);
        cbar();
        const int seq = msi[0];
        if (seq >= NG) break;
        const int m = seq >> 3, b = seq & 7;
        const int g = b * MPTS + m;

        if (tid == 0) {
            while (g_prog[b] <= m) __nanosleep(128);
            __threadfence();
            msf[0] = ldcv(&g_q[3*g]);
            msf[1] = ldcv(&g_q[3*g+1]);
            msf[2] = ldcv(&g_q[3*g+2]);
            msi[1] = 0;
        }
        cbar();
        const float qx = msf[0], qy = msf[1], qz = msf[2];

        // ---- radius candidates (warp-aggregated compaction) ----
#pragma unroll 4
        for (int i = tid; i < NPTS; i += 256) {
            float4 p = g_pos4[b * NPTS + i];
            float dx = __fadd_rn(qx, -p.x);
            float dy = __fadd_rn(qy, -p.y);
            float dz = __fadd_rn(qz, -p.z);
            float d2 = __fadd_rn(__fadd_rn(__fmul_rn(dx,dx), __fmul_rn(dy,dy)),
                                 __fmul_rn(dz,dz));
            bool keep = (d2 <= R2);
            unsigned msk = __ballot_sync(0xffffffffu, keep);
            int basew = 0;
            if (lane == 0 && msk) basew = atomicAdd(&msi[1], __popc(msk));
            basew = __shfl_sync(0xffffffffu, basew, 0);
            if (keep) {
                int ofs = basew + __popc(msk & ((1u << lane) - 1u));
                if (ofs < CAP) { sm[CDO + ofs] = d2; ci[ofs] = i; }
            }
        }
        cbar();
        int cnt = msi[1]; if (cnt > CAP) cnt = CAP;

        // ---- rank-select 64 nearest (stable: smaller d2, then lower idx) ----
        if (cnt > KNBR) {
            for (int t = tid; t < cnt; t += 256) {
                float di = sm[CDO + t]; int ii = ci[t];
                int r = 0;
                for (int j2 = 0; j2 < cnt; j2++) {
                    float dj = sm[CDO + j2];
                    r += (int)((dj < di) | ((dj == di) & (ci[j2] < ii)));
                }
                if (r < KNBR) nl[r] = ii;
            }
        } else {
            for (int t = tid; t < cnt; t += 256) nl[t] = ci[t];
        }
        cbar();
        if (cnt > KNBR) cnt = KNBR;

        // ---- gather feat rows, split into tf32 hi/lo ----
        {
            int j = nl[(e < cnt) ? e : 0];
            const float4* xr = (const float4*)(x + ((size_t)b * NPTS + j) * FDIM) + sub * 4;
#pragma unroll
            for (int i = 0; i < 4; i++) {
                float4 v = xr[i];
                float4 h4, l4;
                h4.x = tf32r(v.x); l4.x = tf32r(v.x - h4.x);
                h4.y = tf32r(v.y); l4.y = tf32r(v.y - h4.y);
                h4.z = tf32r(v.z); l4.z = tf32r(v.z - h4.z);
                h4.w = tf32r(v.w); l4.w = tf32r(v.w - h4.w);
                *(float4*)(sm + FH + e*68 + sub*16 + i*4) = h4;
                *(float4*)(sm + FL + e*68 + sub*16 + i*4) = l4;
            }
            if (sub == 0) {
                float4 pr = g_pos4[b * NPTS + j];
                float d0 = __fadd_rn(pr.x, -qx);
                float d1 = __fadd_rn(pr.y, -qy);
                float d2v = __fadd_rn(pr.z, -qz);
                float h;
                h = tf32r(d0);  sm[FH + e*68 + 64] = h; sm[FL + e*68 + 64] = tf32r(d0 - h);
                h = tf32r(d1);  sm[FH + e*68 + 65] = h; sm[FL + e*68 + 65] = tf32r(d1 - h);
                h = tf32r(d2v); sm[FH + e*68 + 66] = h; sm[FL + e*68 + 66] = tf32r(d2v - h);
                sm[FH + e*68 + 67] = 0.0f; sm[FL + e*68 + 67] = 0.0f;
            }
        }
        cbar();

        // ---- layer 1: FEAT[64x68] x W1[68x64] -> H1 ----
        {
            float c[4][4];
#pragma unroll
            for (int nt = 0; nt < 4; nt++)
#pragma unroll
                for (int q = 0; q < 4; q++) c[nt][q] = 0.0f;
            const int r0 = (mr + lr) * 68, r1 = (mr + lr + 8) * 68;
#pragma unroll
            for (int ks = 0; ks < 8; ks++) {
                const int kb = ks * 8 + lc;
                unsigned ah[4], al[4];
                ah[0] = __float_as_uint(sm[FH + r0 + kb]);
                ah[1] = __float_as_uint(sm[FH + r1 + kb]);
                ah[2] = __float_as_uint(sm[FH + r0 + kb + 4]);
                ah[3] = __float_as_uint(sm[FH + r1 + kb + 4]);
                al[0] = __float_as_uint(sm[FL + r0 + kb]);
                al[1] = __float_as_uint(sm[FL + r1 + kb]);
                al[2] = __float_as_uint(sm[FL + r0 + kb + 4]);
                al[3] = __float_as_uint(sm[FL + r1 + kb + 4]);
#pragma unroll
                for (int nt = 0; nt < 4; nt++) {
                    const int cb = (half*4 + nt) * 8 + lr;   // B col for this lane
                    unsigned bh[2], bl[2];
                    bh[0] = __float_as_uint(sm[W1H + cb*68 + kb]);
                    bh[1] = __float_as_uint(sm[W1H + cb*68 + kb + 4]);
                    bl[0] = __float_as_uint(sm[W1L + cb*68 + kb]);
                    bl[1] = __float_as_uint(sm[W1L + cb*68 + kb + 4]);
                    mma8(c[nt], ah, bh);
                    mma8(c[nt], ah, bl);
                    mma8(c[nt], al, bh);
                }
            }
            {   // k4 tail: k = 64..67
                const int kb = 64 + lc;
                unsigned ah[2], al[2];
                ah[0] = __float_as_uint(sm[FH + r0 + kb]);
                ah[1] = __float_as_uint(sm[FH + r1 + kb]);
                al[0] = __float_as_uint(sm[FL + r0 + kb]);
                al[1] = __float_as_uint(sm[FL + r1 + kb]);
#pragma unroll
                for (int nt = 0; nt < 4; nt++) {
                    const int cb = (half*4 + nt) * 8 + lr;
                    unsigned bh0 = __float_as_uint(sm[W1H + cb*68 + kb]);
                    unsigned bl0 = __float_as_uint(sm[W1L + cb*68 + kb]);
                    mma4(c[nt], ah, bh0);
                    mma4(c[nt], ah, bl0);
                    mma4(c[nt], al, bh0);
                }
            }
#pragma unroll
            for (int nt = 0; nt < 4; nt++) {
                const int col = (half*4 + nt) * 8 + 2*lc;
                const int ra = mr + lr, rb = ra + 8;
                float v, h;
                v = fmaxf(c[nt][0] + sm[B1O + col], 0.0f);
                h = tf32r(v); sm[H1H + ra*68 + col] = h; sm[H1L + ra*68 + col] = tf32r(v - h);
                v = fmaxf(c[nt][1] + sm[B1O + col + 1], 0.0f);
                h = tf32r(v); sm[H1H + ra*68 + col + 1] = h; sm[H1L + ra*68 + col + 1] = tf32r(v - h);
                v = fmaxf(c[nt][2] + sm[B1O + col], 0.0f);
                h = tf32r(v); sm[H1H + rb*68 + col] = h; sm[H1L + rb*68 + col] = tf32r(v - h);
                v = fmaxf(c[nt][3] + sm[B1O + col + 1], 0.0f);
                h = tf32r(v); sm[H1H + rb*68 + col + 1] = h; sm[H1L + rb*68 + col + 1] = tf32r(v - h);
            }
        }
        cbar();

        // ---- layer 2: H1 x W2 -> H2 (stored in FEAT buffers) ----
        {
            float c[4][4];
#pragma unroll
            for (int nt = 0; nt < 4; nt++)
#pragma unroll
                for (int q = 0; q < 4; q++) c[nt][q] = 0.0f;
            const int r0 = (mr + lr) * 68, r1 = (mr + lr + 8) * 68;
#pragma unroll
            for (int ks = 0; ks < 8; ks++) {
                const int kb = ks * 8 + lc;
                unsigned ah[4], al[4];
                ah[0] = __float_as_uint(sm[H1H + r0 + kb]);
                ah[1] = __float_as_uint(sm[H1H + r1 + kb]);
                ah[2] = __float_as_uint(sm[H1H + r0 + kb + 4]);
                ah[3] = __float_as_uint(sm[H1H + r1 + kb + 4]);
                al[0] = __float_as_uint(sm[H1L + r0 + kb]);
                al[1] = __float_as_uint(sm[H1L + r1 + kb]);
                al[2] = __float_as_uint(sm[H1L + r0 + kb + 4]);
                al[3] = __float_as_uint(sm[H1L + r1 + kb + 4]);
#pragma unroll
                for (int nt = 0; nt < 4; nt++) {
                    const int cb = (half*4 + nt) * 8 + lr;
                    unsigned bh[2], bl[2];
                    bh[0] = __float_as_uint(sm[W2H + cb*68 + kb]);
                    bh[1] = __float_as_uint(sm[W2H + cb*68 + kb + 4]);
                    bl[0] = __float_as_uint(sm[W2L + cb*68 + kb]);
                    bl[1] = __float_as_uint(sm[W2L + cb*68 + kb + 4]);
                    mma8(c[nt], ah, bh);
                    mma8(c[nt], ah, bl);
                    mma8(c[nt], al, bh);
                }
            }
#pragma unroll
            for (int nt = 0; nt < 4; nt++) {
                const int col = (half*4 + nt) * 8 + 2*lc;
                const int ra = mr + lr, rb = ra + 8;
                float v, h;
                v = fmaxf(c[nt][0] + sm[B2O + col], 0.0f);
                h = tf32r(v); sm[FH + ra*68 + col] = h; sm[FL + ra*68 + col] = tf32r(v - h);
                v = fmaxf(c[nt][1] + sm[B2O + col + 1], 0.0f);
                h = tf32r(v); sm[FH + ra*68 + col + 1] = h; sm[FL + ra*68 + col + 1] = tf32r(v - h);
                v = fmaxf(c[nt][2] + sm[B2O + col], 0.0f);
                h = tf32r(v); sm[FH + rb*68 + col] = h; sm[FL + rb*68 + col] = tf32r(v - h);
                v = fmaxf(c[nt][3] + sm[B2O + col + 1], 0.0f);
                h = tf32r(v); sm[FH + rb*68 + col + 1] = h; sm[FL + rb*68 + col + 1] = tf32r(v - h);
            }
        }
        cbar();

        // ---- layer 3: H2 x W3[64x128] -> bias, row-max into RO ----
        {
            float c[8][4];
#pragma unroll
            for (int nt = 0; nt < 8; nt++)
#pragma unroll
                for (int q = 0; q < 4; q++) c[nt][q] = 0.0f;
            const int r0 = (mr + lr) * 68, r1 = (mr + lr + 8) * 68;
#pragma unroll
            for (int ks = 0; ks < 8; ks++) {
                const int kb = ks * 8 + lc;
                unsigned ah[4], al[4];
                ah[0] = __float_as_uint(sm[FH + r0 + kb]);
                ah[1] = __float_as_uint(sm[FH + r1 + kb]);
                ah[2] = __float_as_uint(sm[FH + r0 + kb + 4]);
                ah[3] = __float_as_uint(sm[FH + r1 + kb + 4]);
                al[0] = __float_as_uint(sm[FL + r0 + kb]);
                al[1] = __float_as_uint(sm[FL + r1 + kb]);
                al[2] = __float_as_uint(sm[FL + r0 + kb + 4]);
                al[3] = __float_as_uint(sm[FL + r1 + kb + 4]);
#pragma unroll
                for (int nt = 0; nt < 8; nt++) {
                    const int cb = (half*8 + nt) * 8 + lr;
                    unsigned bh[2], bl[2];
                    bh[0] = __float_as_uint(sm[W3H + cb*68 + kb]);
                    bh[1] = __float_as_uint(sm[W3H + cb*68 + kb + 4]);
                    bl[0] = __float_as_uint(sm[W3L + cb*68 + kb]);
                    bl[1] = __float_as_uint(sm[W3L + cb*68 + kb + 4]);
                    mma8(c[nt], ah, bh);
                    mma8(c[nt], ah, bl);
                    mma8(c[nt], al, bh);
                }
            }
#pragma unroll
            for (int nt = 0; nt < 8; nt++) {
                const int col = (half*8 + nt) * 8 + 2*lc;
                float v0 = fmaxf(c[nt][0] + sm[B3O + col],     c[nt][2] + sm[B3O + col]);
                float v1 = fmaxf(c[nt][1] + sm[B3O + col + 1], c[nt][3] + sm[B3O + col + 1]);
#pragma unroll
                for (int off = 4; off < 32; off <<= 1) {
                    v0 = fmaxf(v0, __shfl_xor_sync(0xffffffffu, v0, off));
                    v1 = fmaxf(v1, __shfl_xor_sync(0xffffffffu, v1, off));
                }
                if (lane < 4) {
                    sm[ROO + mtile*128 + (half*8 + nt)*8 + 2*lane]     = v0;
                    sm[ROO + mtile*128 + (half*8 + nt)*8 + 2*lane + 1] = v1;
                }
            }
        }
        cbar();

        if (tid < 128) {
            float mm = sm[ROO + tid];
            mm = fmaxf(mm, sm[ROO + 128 + tid]);
            mm = fmaxf(mm, sm[ROO + 256 + tid]);
            mm = fmaxf(mm, sm[ROO + 384 + tid]);
            dout[(size_t)g * 128 + tid] = fmaxf(mm, 0.0f);
        }
        cbar();   // protect smem reuse next iteration
    }
}

// ============================================================================
extern "C" void kernel_launch(void* const* d_in, const int* in_sizes, int n_in,
                              void* d_out, int out_size)
{
    const float* x   = (const float*)d_in[0];
    const float* pos = (const float*)d_in[1];
    const float* W1 = (const float*)d_in[3];
    const float* b1 = (const float*)d_in[4];
    const float* W2 = (const float*)d_in[5];
    const float* b2 = (const float*)d_in[6];
    const float* W3 = (const float*)d_in[7];
    const float* b3 = (const float*)d_in[8];
    float* out = (float*)d_out;

    const int fused_smem = SM_TOT * sizeof(float);   // 214,400 B -> 1 CTA/SM
    cudaFuncSetAttribute(fused_kernel, cudaFuncAttributeMaxDynamicSharedMemorySize,
                         fused_smem);

    init_kernel<<<(BATCH * NPTS + 255) / 256, 256>>>(pos);
    fused_kernel<<<148, 512, fused_smem>>>(x, pos, W1, b1, W2, b2, W3, b3,
                                           out, out_size);
}